// round 2
// baseline (speedup 1.0000x reference)
#include <cuda_runtime.h>
#include <math.h>
#include <stdint.h>

#define B_  2
#define S_  2048
#define D_  1024
#define H_  16
#define HD_ 64

#define TQ 16
#define KC 64
#define KSTRIDE 67   // 64 dims padded to 67 words: (67*k + lane) % 32 conflict-free

// Scratch (allocation-free rule: __device__ globals)
__device__ float g_q [B_*S_*D_];
__device__ float g_k [B_*S_*D_];
__device__ float g_v [B_*S_*D_];
__device__ float g_ao[B_*S_*D_];

// ---------------------------------------------------------------------------
// GEMM: C[M,N] = A[M,K] @ W[N,K]^T + bias[N]     (torch Linear convention)
// 128x128 tile, BK=8, 256 threads, 8x8 per thread.
// ---------------------------------------------------------------------------
__global__ __launch_bounds__(256)
void gemm_xwT(const float* __restrict__ A, const float* __restrict__ W,
              const float* __restrict__ bias, float* __restrict__ C,
              int M, int N, int K)
{
    const int BM = 128, BN = 128, BK = 8;
    __shared__ float As[BK][BM];
    __shared__ float Bs[BK][BN];

    int tid = threadIdx.x;
    int m0 = blockIdx.y * BM;
    int n0 = blockIdx.x * BN;
    int tx = tid & 15;        // 16 col-groups
    int ty = tid >> 4;        // 16 row-groups
    int lrow = tid >> 1;                 // 0..127
    int lcol = (tid & 1) << 2;           // 0 or 4

    const float* Ag = A + (size_t)(m0 + lrow) * K + lcol;
    const float* Wg = W + (size_t)(n0 + lrow) * K + lcol;

    float acc[8][8];
    #pragma unroll
    for (int i = 0; i < 8; i++)
        #pragma unroll
        for (int j = 0; j < 8; j++) acc[i][j] = 0.f;

    for (int k0 = 0; k0 < K; k0 += BK) {
        float4 a4 = *(const float4*)(Ag + k0);
        float4 b4 = *(const float4*)(Wg + k0);
        As[lcol+0][lrow] = a4.x; As[lcol+1][lrow] = a4.y;
        As[lcol+2][lrow] = a4.z; As[lcol+3][lrow] = a4.w;
        Bs[lcol+0][lrow] = b4.x; Bs[lcol+1][lrow] = b4.y;
        Bs[lcol+2][lrow] = b4.z; Bs[lcol+3][lrow] = b4.w;
        __syncthreads();

        #pragma unroll
        for (int k = 0; k < BK; k++) {
            float a[8], b[8];
            #pragma unroll
            for (int i = 0; i < 8; i++) { a[i] = As[k][ty*8 + i]; b[i] = Bs[k][tx*8 + i]; }
            #pragma unroll
            for (int i = 0; i < 8; i++)
                #pragma unroll
                for (int j = 0; j < 8; j++)
                    acc[i][j] += a[i] * b[j];
        }
        __syncthreads();
    }

    #pragma unroll
    for (int i = 0; i < 8; i++) {
        int row = m0 + ty*8 + i;
        float* Crow = C + (size_t)row * N + n0 + tx*8;
        #pragma unroll
        for (int j = 0; j < 8; j++)
            Crow[j] = acc[i][j] + bias[n0 + tx*8 + j];
    }
}

// ---------------------------------------------------------------------------
// Fused causal attention for a tile of TQ=16 queries of one (b,h).
// All 16 score rows (16 x 2048 fp32) live in shared memory: exact softmax,
// single normalized write of attn_weights, and AV reads P from smem.
// ---------------------------------------------------------------------------
__global__ __launch_bounds__(256)
void attn_fused(const float* __restrict__ Q, const float* __restrict__ K,
                const float* __restrict__ V, float* __restrict__ attnw,
                float* __restrict__ AO)
{
    extern __shared__ float sm[];
    float* rows = sm;                       // TQ * S_            (131072 B)
    float* Ks   = sm + TQ * S_;             // KC * KSTRIDE       (K tile, reused for V)
    float* Qs   = Ks + KC * KSTRIDE;        // TQ * HD_

    const int qt = blockIdx.x, h = blockIdx.y, b = blockIdx.z;
    const int q0 = qt * TQ;
    const int tid  = threadIdx.x;
    const int lane = tid & 31;
    const int wid  = tid >> 5;              // 8 warps; warp owns rows 2w, 2w+1
    const int nk   = q0 + TQ;               // keys needed: [0, nk)
    const int nChunk = (nk + KC - 1) / KC;
    const int nkc = nChunk * KC;
    const float scale = 0.125f;             // 1/sqrt(64)

    const float* Qbase = Q + ((size_t)(b*S_ + q0)) * D_ + h*HD_;
    const float* Kbase = K + ((size_t)b*S_) * D_ + h*HD_;
    const float* Vbase = V + ((size_t)b*S_) * D_ + h*HD_;

    // Load Q tile [TQ][HD]
    for (int i = tid; i < TQ*HD_; i += 256)
        Qs[(i >> 6) * HD_ + (i & 63)] = Qbase[(size_t)(i >> 6) * D_ + (i & 63)];

    // ---- Phase 1: scores ----
    const int r0 = 2*wid, r1 = r0 + 1;
    for (int c = 0; c < nChunk; c++) {
        const int k0c = c * KC;
        __syncthreads();    // protects Ks reuse across iterations (and Qs on c==0)
        for (int i = tid; i < KC*HD_; i += 256)
            Ks[(i >> 6) * KSTRIDE + (i & 63)] =
                Kbase[(size_t)(k0c + (i >> 6)) * D_ + (i & 63)];
        __syncthreads();

        float acc00 = 0.f, acc01 = 0.f, acc10 = 0.f, acc11 = 0.f;
        const float* q0p = Qs + r0 * HD_;
        const float* q1p = Qs + r1 * HD_;
        const float* k0p = Ks + lane * KSTRIDE;
        const float* k1p = Ks + (lane + 32) * KSTRIDE;
        #pragma unroll 16
        for (int d = 0; d < HD_; d++) {
            float qa = q0p[d], qb = q1p[d];
            float ka = k0p[d], kb = k1p[d];
            acc00 += qa*ka; acc01 += qa*kb;
            acc10 += qb*ka; acc11 += qb*kb;
        }
        const int kg0 = k0c + lane, kg1 = k0c + lane + 32;
        rows[(size_t)r0*S_ + kg0] = (kg0 <= q0 + r0) ? acc00*scale : -INFINITY;
        rows[(size_t)r0*S_ + kg1] = (kg1 <= q0 + r0) ? acc01*scale : -INFINITY;
        rows[(size_t)r1*S_ + kg0] = (kg0 <= q0 + r1) ? acc10*scale : -INFINITY;
        rows[(size_t)r1*S_ + kg1] = (kg1 <= q0 + r1) ? acc11*scale : -INFINITY;
    }
    __syncthreads();

    // ---- Phase 2: exact softmax per row (warp w handles rows 2w, 2w+1) ----
    #pragma unroll
    for (int rr = 0; rr < 2; rr++) {
        const int r = 2*wid + rr;
        float* prow = rows + (size_t)r * S_;
        float m = -INFINITY;
        for (int i = lane; i < nkc; i += 32) m = fmaxf(m, prow[i]);
        #pragma unroll
        for (int off = 16; off; off >>= 1) m = fmaxf(m, __shfl_xor_sync(0xffffffffu, m, off));
        float s = 0.f;
        for (int i = lane; i < nkc; i += 32) {
            float e = __expf(prow[i] - m);
            prow[i] = e;
            s += e;
        }
        #pragma unroll
        for (int off = 16; off; off >>= 1) s += __shfl_xor_sync(0xffffffffu, s, off);
        float inv = 1.f / s;
        for (int i = lane; i < nkc; i += 32) prow[i] *= inv;
    }
    __syncthreads();

    // ---- Phase 3: write normalized attn_weights (incl. zeros beyond causal) ----
    {
        size_t abase = (((size_t)b * H_ + h) * S_ + q0) * (size_t)S_;
        for (int i = tid; i < TQ * S_; i += 256) {
            int r   = i >> 11;          // / S_
            int col = i & (S_ - 1);
            float v = 0.f;
            if (col <= q0 + r) v = rows[(size_t)r * S_ + col];
            attnw[abase + (size_t)r * S_ + col] = v;
        }
    }

    // ---- Phase 4: AV (accumulators persist across chunks) ----
    float o00 = 0.f, o01 = 0.f, o10 = 0.f, o11 = 0.f;
    const int dA = lane, dB = lane + 32;
    for (int c = 0; c < nChunk; c++) {
        const int k0c = c * KC;
        __syncthreads();    // protects Ks(=Vs) reuse
        for (int i = tid; i < KC*HD_; i += 256)
            Ks[(i >> 6) * KSTRIDE + (i & 63)] =
                Vbase[(size_t)(k0c + (i >> 6)) * D_ + (i & 63)];
        __syncthreads();

        const float* pr0 = rows + (size_t)r0 * S_ + k0c;
        const float* pr1 = rows + (size_t)r1 * S_ + k0c;
        #pragma unroll 8
        for (int k = 0; k < KC; k++) {      // masked tail has p == 0, contributes nothing
            float p0 = pr0[k], p1 = pr1[k];
            float va = Ks[k * KSTRIDE + dA], vb = Ks[k * KSTRIDE + dB];
            o00 += p0*va; o01 += p0*vb;
            o10 += p1*va; o11 += p1*vb;
        }
    }
    {
        float* Arow0 = AO + ((size_t)(b*S_ + q0 + r0)) * D_ + h*HD_;
        float* Arow1 = AO + ((size_t)(b*S_ + q0 + r1)) * D_ + h*HD_;
        Arow0[dA] = o00; Arow0[dB] = o01;
        Arow1[dA] = o10; Arow1[dB] = o11;
    }
}

// ---------------------------------------------------------------------------
extern "C" void kernel_launch(void* const* d_in, const int* in_sizes, int n_in,
                              void* d_out, int out_size)
{
    const float* x  = (const float*)d_in[0];
    const float* Wq = (const float*)d_in[1];
    const float* bq = (const float*)d_in[2];
    const float* Wk = (const float*)d_in[3];
    const float* bk = (const float*)d_in[4];
    const float* Wv = (const float*)d_in[5];
    const float* bv = (const float*)d_in[6];
    const float* Wo = (const float*)d_in[7];
    const float* bo = (const float*)d_in[8];

    float* out   = (float*)d_out;                       // [B,S,D]
    float* attnw = out + (size_t)B_ * S_ * D_;          // [B,H,S,S]

    float *q, *k, *v, *ao;
    cudaGetSymbolAddress((void**)&q,  g_q);
    cudaGetSymbolAddress((void**)&k,  g_k);
    cudaGetSymbolAddress((void**)&v,  g_v);
    cudaGetSymbolAddress((void**)&ao, g_ao);

    const int M = B_ * S_;           // 4096
    dim3 gemm_grid(D_ / 128, M / 128);

    gemm_xwT<<<gemm_grid, 256>>>(x, Wq, bq, q, M, D_, D_);
    gemm_xwT<<<gemm_grid, 256>>>(x, Wk, bk, k, M, D_, D_);
    gemm_xwT<<<gemm_grid, 256>>>(x, Wv, bv, v, M, D_, D_);

    const int smem_bytes = (TQ * S_ + KC * KSTRIDE + TQ * HD_) * (int)sizeof(float);
    cudaFuncSetAttribute(attn_fused, cudaFuncAttributeMaxDynamicSharedMemorySize, smem_bytes);
    dim3 attn_grid(S_ / TQ, H_, B_);
    attn_fused<<<attn_grid, 256, smem_bytes>>>(q, k, v, attnw, ao);

    gemm_xwT<<<gemm_grid, 256>>>(ao, Wo, bo, out, M, D_, D_);
}

// round 3
// speedup vs baseline: 1.4128x; 1.4128x over previous
#include <cuda_runtime.h>
#include <math.h>
#include <stdint.h>

#define B_  2
#define S_  2048
#define D_  1024
#define H_  16
#define HD_ 64

#define TQ  16
#define KC2 128        // k-chunk for attention (split across 2 warp-groups)
#define KSTRIDE 67     // 64 dims padded: lane*67 % 32 = lane*3 -> conflict-free

// Scratch (allocation-free rule: __device__ globals)
__device__ float g_q [B_*S_*D_];
__device__ float g_k [B_*S_*D_];
__device__ float g_v [B_*S_*D_];
__device__ float g_ao[B_*S_*D_];

// ---------------------------------------------------------------------------
// GEMM: C[M,N] = A[M,K] @ W[N,K]^T + bias[N]
// 128x128 tile, BK=8, 256 threads, 8x8/thread, double-buffered smem,
// LDS.128 fragment loads (a-frags broadcast within half-warp).
// ---------------------------------------------------------------------------
__global__ __launch_bounds__(256)
void gemm_xwT(const float* __restrict__ A, const float* __restrict__ W,
              const float* __restrict__ bias, float* __restrict__ C,
              int M, int N, int K)
{
    const int BM = 128, BN = 128, BK = 8;
    __shared__ float As[2][BK][BM];
    __shared__ float Bs[2][BK][BN];

    int tid = threadIdx.x;
    int m0 = blockIdx.y * BM;
    int n0 = blockIdx.x * BN;
    int tx = tid & 15;
    int ty = tid >> 4;
    int lrow = tid >> 1;
    int lcol = (tid & 1) << 2;

    const float* Ag = A + (size_t)(m0 + lrow) * K + lcol;
    const float* Wg = W + (size_t)(n0 + lrow) * K + lcol;

    float acc[8][8];
    #pragma unroll
    for (int i = 0; i < 8; i++)
        #pragma unroll
        for (int j = 0; j < 8; j++) acc[i][j] = 0.f;

    // prologue: fill buffer 0
    float4 a4 = *(const float4*)(Ag);
    float4 b4 = *(const float4*)(Wg);
    As[0][lcol+0][lrow] = a4.x; As[0][lcol+1][lrow] = a4.y;
    As[0][lcol+2][lrow] = a4.z; As[0][lcol+3][lrow] = a4.w;
    Bs[0][lcol+0][lrow] = b4.x; Bs[0][lcol+1][lrow] = b4.y;
    Bs[0][lcol+2][lrow] = b4.z; Bs[0][lcol+3][lrow] = b4.w;
    __syncthreads();

    int buf = 0;
    for (int k0 = BK; k0 <= K; k0 += BK) {
        if (k0 < K) {
            a4 = *(const float4*)(Ag + k0);
            b4 = *(const float4*)(Wg + k0);
        }
        #pragma unroll
        for (int k = 0; k < BK; k++) {
            float4 af0 = *(const float4*)&As[buf][k][ty*8];
            float4 af1 = *(const float4*)&As[buf][k][ty*8+4];
            float4 bf0 = *(const float4*)&Bs[buf][k][tx*8];
            float4 bf1 = *(const float4*)&Bs[buf][k][tx*8+4];
            float a[8] = {af0.x,af0.y,af0.z,af0.w, af1.x,af1.y,af1.z,af1.w};
            float b[8] = {bf0.x,bf0.y,bf0.z,bf0.w, bf1.x,bf1.y,bf1.z,bf1.w};
            #pragma unroll
            for (int i = 0; i < 8; i++)
                #pragma unroll
                for (int j = 0; j < 8; j++)
                    acc[i][j] += a[i] * b[j];
        }
        if (k0 < K) {
            int nb = buf ^ 1;
            As[nb][lcol+0][lrow] = a4.x; As[nb][lcol+1][lrow] = a4.y;
            As[nb][lcol+2][lrow] = a4.z; As[nb][lcol+3][lrow] = a4.w;
            Bs[nb][lcol+0][lrow] = b4.x; Bs[nb][lcol+1][lrow] = b4.y;
            Bs[nb][lcol+2][lrow] = b4.z; Bs[nb][lcol+3][lrow] = b4.w;
        }
        __syncthreads();
        buf ^= 1;
    }

    #pragma unroll
    for (int i = 0; i < 8; i++) {
        int row = m0 + ty*8 + i;
        float* Crow = C + (size_t)row * N + n0 + tx*8;
        #pragma unroll
        for (int j = 0; j < 8; j++)
            Crow[j] = acc[i][j] + bias[n0 + tx*8 + j];
    }
}

// ---------------------------------------------------------------------------
// Fused causal attention, TQ=16 queries per block, 512 threads (16 warps).
// All 16 score rows (16 x 2048 fp32) in smem -> exact softmax, single
// normalized attn_weights write. k-chunks of 128 split across 2 warp-groups.
// ---------------------------------------------------------------------------
__global__ __launch_bounds__(512)
void attn_fused(const float* __restrict__ Q, const float* __restrict__ K,
                const float* __restrict__ V, float* __restrict__ attnw,
                float* __restrict__ AO)
{
    extern __shared__ float sm[];
    float* rows = sm;                        // TQ * S_            (131072 B)
    float* Ks   = sm + TQ * S_;              // KC2 * KSTRIDE      (K/V tile, reused as pbuf)
    float* Qs   = Ks + KC2 * KSTRIDE;        // TQ * HD_

    const int qt = blockIdx.x, h = blockIdx.y, b = blockIdx.z;
    const int q0 = qt * TQ;
    const int tid  = threadIdx.x;
    const int lane = tid & 31;
    const int wid  = tid >> 5;               // 16 warps
    const int wk   = wid >> 3;               // k-half: 0 or 1
    const int wr   = wid & 7;                // row-pair id
    const int r0 = 2*wr, r1 = r0 + 1;
    const int nk   = q0 + TQ;
    const int nChunk = (nk + KC2 - 1) / KC2;
    const int nkc = nChunk * KC2;
    const float scale = 0.125f;              // 1/sqrt(64)

    const float* Qbase = Q + ((size_t)(b*S_ + q0)) * D_ + h*HD_;
    const float* Kbase = K + ((size_t)b*S_) * D_ + h*HD_;
    const float* Vbase = V + ((size_t)b*S_) * D_ + h*HD_;

    // Load Q tile [TQ][HD]
    for (int i = tid; i < TQ*HD_; i += 512)
        Qs[i] = Qbase[(size_t)(i >> 6) * D_ + (i & 63)];

    // ---- Phase 1: scores ----
    for (int c = 0; c < nChunk; c++) {
        const int k0c = c * KC2;
        __syncthreads();    // Ks reuse across iterations (and Qs on c==0)
        for (int i = tid; i < KC2*(HD_/4); i += 512) {
            int row = i >> 4, c4 = (i & 15) << 2;
            float4 t = *(const float4*)(Kbase + (size_t)(k0c + row) * D_ + c4);
            float* dst = Ks + row * KSTRIDE + c4;
            dst[0] = t.x; dst[1] = t.y; dst[2] = t.z; dst[3] = t.w;
        }
        __syncthreads();

        float acc00 = 0.f, acc01 = 0.f, acc10 = 0.f, acc11 = 0.f;
        const float* q0p = Qs + r0 * HD_;
        const float* q1p = Qs + r1 * HD_;
        const float* k0p = Ks + (wk*64 + lane) * KSTRIDE;
        const float* k1p = k0p + 32 * KSTRIDE;
        #pragma unroll 16
        for (int d = 0; d < HD_; d++) {
            float qa = q0p[d], qb = q1p[d];
            float ka = k0p[d], kb = k1p[d];
            acc00 += qa*ka; acc01 += qa*kb;
            acc10 += qb*ka; acc11 += qb*kb;
        }
        const int kg0 = k0c + wk*64 + lane, kg1 = kg0 + 32;
        rows[(size_t)r0*S_ + kg0] = (kg0 <= q0 + r0) ? acc00*scale : -INFINITY;
        rows[(size_t)r0*S_ + kg1] = (kg1 <= q0 + r0) ? acc01*scale : -INFINITY;
        rows[(size_t)r1*S_ + kg0] = (kg0 <= q0 + r1) ? acc10*scale : -INFINITY;
        rows[(size_t)r1*S_ + kg1] = (kg1 <= q0 + r1) ? acc11*scale : -INFINITY;
    }
    __syncthreads();

    // ---- Phase 2: exact softmax, one warp per row ----
    {
        const int r = wid;                   // 16 warps <-> 16 rows
        float* prow = rows + (size_t)r * S_;
        float m = -INFINITY;
        for (int i = lane; i < nkc; i += 32) m = fmaxf(m, prow[i]);
        #pragma unroll
        for (int off = 16; off; off >>= 1) m = fmaxf(m, __shfl_xor_sync(0xffffffffu, m, off));
        float s = 0.f;
        for (int i = lane; i < nkc; i += 32) {
            float e = __expf(prow[i] - m);
            prow[i] = e;
            s += e;
        }
        #pragma unroll
        for (int off = 16; off; off >>= 1) s += __shfl_xor_sync(0xffffffffu, s, off);
        float inv = 1.f / s;
        for (int i = lane; i < nkc; i += 32) prow[i] *= inv;
    }
    __syncthreads();

    // ---- Phase 3: write normalized attn_weights ----
    {
        size_t abase = (((size_t)b * H_ + h) * S_ + q0) * (size_t)S_;
        for (int i = tid; i < TQ * S_; i += 512) {
            int r   = i >> 11;
            int col = i & (S_ - 1);
            float v = 0.f;
            if (col <= q0 + r) v = rows[(size_t)r * S_ + col];
            attnw[abase + (size_t)r * S_ + col] = v;
        }
    }

    // ---- Phase 4: AV; each warp-group handles its k-half of every chunk ----
    float o00 = 0.f, o01 = 0.f, o10 = 0.f, o11 = 0.f;
    const int dA = lane, dB = lane + 32;
    for (int c = 0; c < nChunk; c++) {
        const int k0c = c * KC2;
        __syncthreads();    // Ks reuse
        for (int i = tid; i < KC2*(HD_/4); i += 512) {
            int row = i >> 4, c4 = (i & 15) << 2;
            float4 t = *(const float4*)(Vbase + (size_t)(k0c + row) * D_ + c4);
            float* dst = Ks + row * KSTRIDE + c4;
            dst[0] = t.x; dst[1] = t.y; dst[2] = t.z; dst[3] = t.w;
        }
        __syncthreads();

        const float* pr0 = rows + (size_t)r0 * S_ + k0c + wk*64;
        const float* pr1 = rows + (size_t)r1 * S_ + k0c + wk*64;
        const float* vb0 = Ks + (wk*64) * KSTRIDE;
        #pragma unroll 8
        for (int k = 0; k < 64; k++) {       // masked tail has p == 0
            float p0 = pr0[k], p1 = pr1[k];
            float va = vb0[k * KSTRIDE + dA], vv = vb0[k * KSTRIDE + dB];
            o00 += p0*va; o01 += p0*vv;
            o10 += p1*va; o11 += p1*vv;
        }
    }

    // combine the two k-half partials via smem (reuse Ks area)
    float* pbuf = Ks;                        // 16 rows x 64 d = 4KB
    __syncthreads();
    if (wk == 1) {
        pbuf[r0*HD_ + dA] = o00; pbuf[r0*HD_ + dB] = o01;
        pbuf[r1*HD_ + dA] = o10; pbuf[r1*HD_ + dB] = o11;
    }
    __syncthreads();
    if (wk == 0) {
        float* Arow0 = AO + ((size_t)(b*S_ + q0 + r0)) * D_ + h*HD_;
        float* Arow1 = AO + ((size_t)(b*S_ + q0 + r1)) * D_ + h*HD_;
        Arow0[dA] = o00 + pbuf[r0*HD_ + dA];
        Arow0[dB] = o01 + pbuf[r0*HD_ + dB];
        Arow1[dA] = o10 + pbuf[r1*HD_ + dA];
        Arow1[dB] = o11 + pbuf[r1*HD_ + dB];
    }
}

// ---------------------------------------------------------------------------
extern "C" void kernel_launch(void* const* d_in, const int* in_sizes, int n_in,
                              void* d_out, int out_size)
{
    const float* x  = (const float*)d_in[0];
    const float* Wq = (const float*)d_in[1];
    const float* bq = (const float*)d_in[2];
    const float* Wk = (const float*)d_in[3];
    const float* bk = (const float*)d_in[4];
    const float* Wv = (const float*)d_in[5];
    const float* bv = (const float*)d_in[6];
    const float* Wo = (const float*)d_in[7];
    const float* bo = (const float*)d_in[8];

    float* out   = (float*)d_out;                       // [B,S,D]
    float* attnw = out + (size_t)B_ * S_ * D_;          // [B,H,S,S]

    float *q, *k, *v, *ao;
    cudaGetSymbolAddress((void**)&q,  g_q);
    cudaGetSymbolAddress((void**)&k,  g_k);
    cudaGetSymbolAddress((void**)&v,  g_v);
    cudaGetSymbolAddress((void**)&ao, g_ao);

    const int M = B_ * S_;           // 4096
    dim3 gemm_grid(D_ / 128, M / 128);

    gemm_xwT<<<gemm_grid, 256>>>(x, Wq, bq, q, M, D_, D_);
    gemm_xwT<<<gemm_grid, 256>>>(x, Wk, bk, k, M, D_, D_);
    gemm_xwT<<<gemm_grid, 256>>>(x, Wv, bv, v, M, D_, D_);

    const int smem_bytes = (TQ * S_ + KC2 * KSTRIDE + TQ * HD_) * (int)sizeof(float);
    cudaFuncSetAttribute(attn_fused, cudaFuncAttributeMaxDynamicSharedMemorySize, smem_bytes);
    dim3 attn_grid(S_ / TQ, H_, B_);
    attn_fused<<<attn_grid, 512, smem_bytes>>>(q, k, v, attnw, ao);

    gemm_xwT<<<gemm_grid, 256>>>(ao, Wo, bo, out, M, D_, D_);
}

// round 5
// speedup vs baseline: 1.7716x; 1.2540x over previous
#include <cuda_runtime.h>
#include <cuda_bf16.h>
#include <math.h>
#include <stdint.h>

#define B_  2
#define S_  2048
#define D_  1024
#define H_  16
#define HD_ 64

#define TQ  16
#define KC2 128
#define KSTRIDE 67

#define MSZ (B_*S_)          // 4096 rows

// ---------------------------------------------------------------------------
// Scratch (allocation-free rule: __device__ globals)
// ---------------------------------------------------------------------------
__device__ float g_q [B_*S_*D_];
__device__ float g_k [B_*S_*D_];
__device__ float g_v [B_*S_*D_];
__device__ float g_ao[B_*S_*D_];

__device__ __nv_bfloat16 g_xhi[MSZ*D_];
__device__ __nv_bfloat16 g_xlo[MSZ*D_];
__device__ __nv_bfloat16 g_whi[4*D_*D_];   // Wq, Wk, Wv, Wo
__device__ __nv_bfloat16 g_wlo[4*D_*D_];
__device__ __nv_bfloat16 g_aohi[MSZ*D_];
__device__ __nv_bfloat16 g_aolo[MSZ*D_];

// ---------------------------------------------------------------------------
// fp32 -> bf16 (hi, lo) split
// ---------------------------------------------------------------------------
__global__ __launch_bounds__(256)
void convert_split(const float4* __restrict__ in,
                   uint2* __restrict__ hi, uint2* __restrict__ lo, int n4)
{
    int i = blockIdx.x * 256 + threadIdx.x;
    if (i >= n4) return;
    float4 v = in[i];
    __nv_bfloat162 h0 = __floats2bfloat162_rn(v.x, v.y);
    __nv_bfloat162 h1 = __floats2bfloat162_rn(v.z, v.w);
    __nv_bfloat162 l0 = __floats2bfloat162_rn(v.x - __bfloat162float(h0.x),
                                              v.y - __bfloat162float(h0.y));
    __nv_bfloat162 l1 = __floats2bfloat162_rn(v.z - __bfloat162float(h1.x),
                                              v.w - __bfloat162float(h1.y));
    uint2 H, L;
    H.x = *(const uint32_t*)&h0; H.y = *(const uint32_t*)&h1;
    L.x = *(const uint32_t*)&l0; L.y = *(const uint32_t*)&l1;
    hi[i] = H; lo[i] = L;
}

// ---------------------------------------------------------------------------
// PTX helpers (non-variant ISA: works on plain sm_103 target)
// ---------------------------------------------------------------------------
__device__ __forceinline__ uint32_t smem_u32(const void* p) {
    uint32_t a;
    asm("{ .reg .u64 t; cvta.to.shared.u64 t, %1; cvt.u32.u64 %0, t; }" : "=r"(a) : "l"(p));
    return a;
}
__device__ __forceinline__ void ldm_x4(uint32_t* r, uint32_t addr) {
    asm volatile("ldmatrix.sync.aligned.m8n8.x4.shared.b16 {%0,%1,%2,%3}, [%4];"
        : "=r"(r[0]), "=r"(r[1]), "=r"(r[2]), "=r"(r[3]) : "r"(addr));
}
__device__ __forceinline__ void mma_bf16(float* c, const uint32_t* a,
                                         uint32_t b0, uint32_t b1) {
    asm volatile(
        "mma.sync.aligned.m16n8k16.row.col.f32.bf16.bf16.f32 "
        "{%0,%1,%2,%3}, {%4,%5,%6,%7}, {%8,%9}, {%0,%1,%2,%3};"
        : "+f"(c[0]), "+f"(c[1]), "+f"(c[2]), "+f"(c[3])
        : "r"(a[0]), "r"(a[1]), "r"(a[2]), "r"(a[3]), "r"(b0), "r"(b1));
}

// ---------------------------------------------------------------------------
// HMMA GEMM: C[M,N] = A[M,K] @ W[N,K]^T + bias,  bf16 hi/lo split, f32 accum.
// 128x128 tile/CTA, K-chunks of 32, 8 warps (2 M-halves x 4 N-quarters).
// ---------------------------------------------------------------------------
#define LDT 40   // bf16 row stride in smem (80 B): conflict-free for ldmatrix

__global__ __launch_bounds__(256)
void gemm_hmma(const __nv_bfloat16* __restrict__ Ahi, const __nv_bfloat16* __restrict__ Alo,
               const __nv_bfloat16* __restrict__ Bhi, const __nv_bfloat16* __restrict__ Blo,
               const float* __restrict__ bias, float* __restrict__ C,
               int M, int N, int K)
{
    __shared__ __nv_bfloat16 sA[2][128*LDT];   // [hi/lo][row*LDT + k]
    __shared__ __nv_bfloat16 sB[2][128*LDT];

    const int tid = threadIdx.x;
    const int lane = tid & 31;
    const int wid  = tid >> 5;
    const int wm = wid & 1;      // M half (64 rows)
    const int wn = wid >> 1;     // N quarter (32 cols)
    const int m0 = blockIdx.y * 128;
    const int n0 = blockIdx.x * 128;

    // ldmatrix per-lane addressing
    const int sub = lane >> 3, rr = lane & 7;
    const int rowoff = ((sub & 1) << 3) + rr;
    const int koffb  = (sub >> 1) << 4;          // 0 or 16 bytes

    const uint32_t aHi = smem_u32(sA[0]) + (uint32_t)((wm*64 + rowoff) * (LDT*2) + koffb);
    const uint32_t aLo = smem_u32(sA[1]) + (uint32_t)((wm*64 + rowoff) * (LDT*2) + koffb);
    const uint32_t bHi = smem_u32(sB[0]) + (uint32_t)((wn*32 + rowoff) * (LDT*2) + koffb);
    const uint32_t bLo = smem_u32(sB[1]) + (uint32_t)((wn*32 + rowoff) * (LDT*2) + koffb);

    float acc[4][4][4];
    #pragma unroll
    for (int i = 0; i < 4; i++)
        #pragma unroll
        for (int j = 0; j < 4; j++)
            #pragma unroll
            for (int q = 0; q < 4; q++) acc[i][j][q] = 0.f;

    for (int k0 = 0; k0 < K; k0 += 32) {
        __syncthreads();
        // fill 4 tiles: Ahi, Alo, Bhi, Blo (128 rows x 32 bf16 each)
        #pragma unroll
        for (int buf = 0; buf < 4; buf++) {
            const __nv_bfloat16* g =
                (buf == 0) ? Ahi + (size_t)m0 * K :
                (buf == 1) ? Alo + (size_t)m0 * K :
                (buf == 2) ? Bhi + (size_t)n0 * K :
                             Blo + (size_t)n0 * K;
            __nv_bfloat16* s = (buf < 2) ? sA[buf] : sB[buf - 2];
            #pragma unroll
            for (int it = 0; it < 2; it++) {
                int idx = it * 256 + tid;          // 0..511
                int row = idx >> 2, vv = idx & 3;
                uint4 t = *(const uint4*)(g + (size_t)row * K + k0 + vv * 8);
                *(uint4*)(s + row * LDT + vv * 8) = t;
            }
        }
        __syncthreads();

        #pragma unroll
        for (int ks = 0; ks < 2; ks++) {
            const uint32_t kb = (uint32_t)(ks * 32);
            uint32_t ah[4][4], bh[2][4], bl[2][4];
            #pragma unroll
            for (int mt = 0; mt < 4; mt++) ldm_x4(ah[mt], aHi + mt * (16*LDT*2) + kb);
            ldm_x4(bh[0], bHi + kb);
            ldm_x4(bh[1], bHi + 16*LDT*2 + kb);
            ldm_x4(bl[0], bLo + kb);
            ldm_x4(bl[1], bLo + 16*LDT*2 + kb);

            #pragma unroll
            for (int mt = 0; mt < 4; mt++)
                #pragma unroll
                for (int nf = 0; nf < 4; nf++) {
                    const int nb = nf >> 1, sel = nf & 1;
                    mma_bf16(acc[mt][nf], ah[mt], bh[nb][sel], bh[nb][2+sel]);
                    mma_bf16(acc[mt][nf], ah[mt], bl[nb][sel], bl[nb][2+sel]);
                }

            uint32_t al[4][4];
            #pragma unroll
            for (int mt = 0; mt < 4; mt++) ldm_x4(al[mt], aLo + mt * (16*LDT*2) + kb);
            #pragma unroll
            for (int mt = 0; mt < 4; mt++)
                #pragma unroll
                for (int nf = 0; nf < 4; nf++) {
                    const int nb = nf >> 1, sel = nf & 1;
                    mma_bf16(acc[mt][nf], al[mt], bh[nb][sel], bh[nb][2+sel]);
                }
        }
    }

    // epilogue
    const int g = lane >> 2, t = lane & 3;
    #pragma unroll
    for (int mt = 0; mt < 4; mt++) {
        const int row = m0 + wm*64 + mt*16 + g;
        #pragma unroll
        for (int nf = 0; nf < 4; nf++) {
            const int col = n0 + wn*32 + nf*8 + t*2;
            const float b0 = bias[col], b1 = bias[col+1];
            float2 lo2 = { acc[mt][nf][0] + b0, acc[mt][nf][1] + b1 };
            float2 hi2 = { acc[mt][nf][2] + b0, acc[mt][nf][3] + b1 };
            *(float2*)(C + (size_t)row * N + col)       = lo2;
            *(float2*)(C + (size_t)(row + 8) * N + col) = hi2;
        }
    }
}

// ---------------------------------------------------------------------------
// Fused causal attention (unchanged, known-good): TQ=16 queries, 512 threads.
// ---------------------------------------------------------------------------
__global__ __launch_bounds__(512)
void attn_fused(const float* __restrict__ Q, const float* __restrict__ K,
                const float* __restrict__ V, float* __restrict__ attnw,
                float* __restrict__ AO)
{
    extern __shared__ float sm[];
    float* rows = sm;
    float* Ks   = sm + TQ * S_;
    float* Qs   = Ks + KC2 * KSTRIDE;

    const int qt = blockIdx.x, h = blockIdx.y, b = blockIdx.z;
    const int q0 = qt * TQ;
    const int tid  = threadIdx.x;
    const int lane = tid & 31;
    const int wid  = tid >> 5;
    const int wk   = wid >> 3;
    const int wr   = wid & 7;
    const int r0 = 2*wr, r1 = r0 + 1;
    const int nk   = q0 + TQ;
    const int nChunk = (nk + KC2 - 1) / KC2;
    const int nkc = nChunk * KC2;
    const float scale = 0.125f;

    const float* Qbase = Q + ((size_t)(b*S_ + q0)) * D_ + h*HD_;
    const float* Kbase = K + ((size_t)b*S_) * D_ + h*HD_;
    const float* Vbase = V + ((size_t)b*S_) * D_ + h*HD_;

    for (int i = tid; i < TQ*HD_; i += 512)
        Qs[i] = Qbase[(size_t)(i >> 6) * D_ + (i & 63)];

    for (int c = 0; c < nChunk; c++) {
        const int k0c = c * KC2;
        __syncthreads();
        for (int i = tid; i < KC2*(HD_/4); i += 512) {
            int row = i >> 4, c4 = (i & 15) << 2;
            float4 t = *(const float4*)(Kbase + (size_t)(k0c + row) * D_ + c4);
            float* dst = Ks + row * KSTRIDE + c4;
            dst[0] = t.x; dst[1] = t.y; dst[2] = t.z; dst[3] = t.w;
        }
        __syncthreads();

        float acc00 = 0.f, acc01 = 0.f, acc10 = 0.f, acc11 = 0.f;
        const float* q0p = Qs + r0 * HD_;
        const float* q1p = Qs + r1 * HD_;
        const float* k0p = Ks + (wk*64 + lane) * KSTRIDE;
        const float* k1p = k0p + 32 * KSTRIDE;
        #pragma unroll 16
        for (int d = 0; d < HD_; d++) {
            float qa = q0p[d], qb = q1p[d];
            float ka = k0p[d], kb = k1p[d];
            acc00 += qa*ka; acc01 += qa*kb;
            acc10 += qb*ka; acc11 += qb*kb;
        }
        const int kg0 = k0c + wk*64 + lane, kg1 = kg0 + 32;
        rows[(size_t)r0*S_ + kg0] = (kg0 <= q0 + r0) ? acc00*scale : -INFINITY;
        rows[(size_t)r0*S_ + kg1] = (kg1 <= q0 + r0) ? acc01*scale : -INFINITY;
        rows[(size_t)r1*S_ + kg0] = (kg0 <= q0 + r1) ? acc10*scale : -INFINITY;
        rows[(size_t)r1*S_ + kg1] = (kg1 <= q0 + r1) ? acc11*scale : -INFINITY;
    }
    __syncthreads();

    {
        const int r = wid;
        float* prow = rows + (size_t)r * S_;
        float m = -INFINITY;
        for (int i = lane; i < nkc; i += 32) m = fmaxf(m, prow[i]);
        #pragma unroll
        for (int off = 16; off; off >>= 1) m = fmaxf(m, __shfl_xor_sync(0xffffffffu, m, off));
        float s = 0.f;
        for (int i = lane; i < nkc; i += 32) {
            float e = __expf(prow[i] - m);
            prow[i] = e;
            s += e;
        }
        #pragma unroll
        for (int off = 16; off; off >>= 1) s += __shfl_xor_sync(0xffffffffu, s, off);
        float inv = 1.f / s;
        for (int i = lane; i < nkc; i += 32) prow[i] *= inv;
    }
    __syncthreads();

    {
        size_t abase = (((size_t)b * H_ + h) * S_ + q0) * (size_t)S_;
        for (int i = tid; i < TQ * S_; i += 512) {
            int r   = i >> 11;
            int col = i & (S_ - 1);
            float v = 0.f;
            if (col <= q0 + r) v = rows[(size_t)r * S_ + col];
            attnw[abase + (size_t)r * S_ + col] = v;
        }
    }

    float o00 = 0.f, o01 = 0.f, o10 = 0.f, o11 = 0.f;
    const int dA = lane, dB = lane + 32;
    for (int c = 0; c < nChunk; c++) {
        const int k0c = c * KC2;
        __syncthreads();
        for (int i = tid; i < KC2*(HD_/4); i += 512) {
            int row = i >> 4, c4 = (i & 15) << 2;
            float4 t = *(const float4*)(Vbase + (size_t)(k0c + row) * D_ + c4);
            float* dst = Ks + row * KSTRIDE + c4;
            dst[0] = t.x; dst[1] = t.y; dst[2] = t.z; dst[3] = t.w;
        }
        __syncthreads();

        const float* pr0 = rows + (size_t)r0 * S_ + k0c + wk*64;
        const float* pr1 = rows + (size_t)r1 * S_ + k0c + wk*64;
        const float* vb0 = Ks + (wk*64) * KSTRIDE;
        #pragma unroll 8
        for (int k = 0; k < 64; k++) {
            float p0 = pr0[k], p1 = pr1[k];
            float va = vb0[k * KSTRIDE + dA], vv = vb0[k * KSTRIDE + dB];
            o00 += p0*va; o01 += p0*vv;
            o10 += p1*va; o11 += p1*vv;
        }
    }

    float* pbuf = Ks;
    __syncthreads();
    if (wk == 1) {
        pbuf[r0*HD_ + dA] = o00; pbuf[r0*HD_ + dB] = o01;
        pbuf[r1*HD_ + dA] = o10; pbuf[r1*HD_ + dB] = o11;
    }
    __syncthreads();
    if (wk == 0) {
        float* Arow0 = AO + ((size_t)(b*S_ + q0 + r0)) * D_ + h*HD_;
        float* Arow1 = AO + ((size_t)(b*S_ + q0 + r1)) * D_ + h*HD_;
        Arow0[dA] = o00 + pbuf[r0*HD_ + dA];
        Arow0[dB] = o01 + pbuf[r0*HD_ + dB];
        Arow1[dA] = o10 + pbuf[r1*HD_ + dA];
        Arow1[dB] = o11 + pbuf[r1*HD_ + dB];
    }
}

// ---------------------------------------------------------------------------
extern "C" void kernel_launch(void* const* d_in, const int* in_sizes, int n_in,
                              void* d_out, int out_size)
{
    const float* x  = (const float*)d_in[0];
    const float* Wq = (const float*)d_in[1];
    const float* bq = (const float*)d_in[2];
    const float* Wk = (const float*)d_in[3];
    const float* bk = (const float*)d_in[4];
    const float* Wv = (const float*)d_in[5];
    const float* bv = (const float*)d_in[6];
    const float* Wo = (const float*)d_in[7];
    const float* bo = (const float*)d_in[8];

    float* out   = (float*)d_out;                       // [B,S,D]
    float* attnw = out + (size_t)B_ * S_ * D_;          // [B,H,S,S]

    float *q, *k, *v, *ao;
    __nv_bfloat16 *xhi, *xlo, *whi, *wlo, *aohi, *aolo;
    cudaGetSymbolAddress((void**)&q,  g_q);
    cudaGetSymbolAddress((void**)&k,  g_k);
    cudaGetSymbolAddress((void**)&v,  g_v);
    cudaGetSymbolAddress((void**)&ao, g_ao);
    cudaGetSymbolAddress((void**)&xhi, g_xhi);
    cudaGetSymbolAddress((void**)&xlo, g_xlo);
    cudaGetSymbolAddress((void**)&whi, g_whi);
    cudaGetSymbolAddress((void**)&wlo, g_wlo);
    cudaGetSymbolAddress((void**)&aohi, g_aohi);
    cudaGetSymbolAddress((void**)&aolo, g_aolo);

    const int M = MSZ;               // 4096
    const int WSZ = D_ * D_;         // 1048576

    // splits
    convert_split<<<(M*D_/4 + 255)/256, 256>>>((const float4*)x,
        (uint2*)xhi, (uint2*)xlo, M*D_/4);
    const float* Ws[4] = { Wq, Wk, Wv, Wo };
    for (int i = 0; i < 4; i++)
        convert_split<<<(WSZ/4 + 255)/256, 256>>>((const float4*)Ws[i],
            (uint2*)(whi + (size_t)i*WSZ), (uint2*)(wlo + (size_t)i*WSZ), WSZ/4);

    dim3 ggrid(D_ / 128, M / 128);   // (8, 32)
    gemm_hmma<<<ggrid, 256>>>(xhi, xlo, whi + 0*(size_t)WSZ, wlo + 0*(size_t)WSZ, bq, q, M, D_, D_);
    gemm_hmma<<<ggrid, 256>>>(xhi, xlo, whi + 1*(size_t)WSZ, wlo + 1*(size_t)WSZ, bk, k, M, D_, D_);
    gemm_hmma<<<ggrid, 256>>>(xhi, xlo, whi + 2*(size_t)WSZ, wlo + 2*(size_t)WSZ, bv, v, M, D_, D_);

    const int smem_bytes = (TQ * S_ + KC2 * KSTRIDE + TQ * HD_) * (int)sizeof(float);
    cudaFuncSetAttribute(attn_fused, cudaFuncAttributeMaxDynamicSharedMemorySize, smem_bytes);
    dim3 attn_grid(S_ / TQ, H_, B_);
    attn_fused<<<attn_grid, 512, smem_bytes>>>(q, k, v, attnw, ao);

    convert_split<<<(M*D_/4 + 255)/256, 256>>>((const float4*)ao,
        (uint2*)aohi, (uint2*)aolo, M*D_/4);
    gemm_hmma<<<ggrid, 256>>>(aohi, aolo, whi + 3*(size_t)WSZ, wlo + 3*(size_t)WSZ, bo, out, M, D_, D_);
}

// round 6
// speedup vs baseline: 2.9766x; 1.6802x over previous
#include <cuda_runtime.h>
#include <cuda_bf16.h>
#include <math.h>
#include <stdint.h>

#define B_  2
#define S_  2048
#define D_  1024
#define H_  16
#define HD_ 64

#define TQ  16
#define KCA 256              // attention key-chunk

#define MSZ (B_*S_)          // 4096 rows

// ---------------------------------------------------------------------------
// Scratch (allocation-free rule: __device__ globals)
// ---------------------------------------------------------------------------
__device__ float g_q [B_*S_*D_];
__device__ float g_k [B_*S_*D_];
__device__ float g_v [B_*S_*D_];
__device__ float g_ao[B_*S_*D_];

__device__ __nv_bfloat16 g_xhi[MSZ*D_];
__device__ __nv_bfloat16 g_xlo[MSZ*D_];
__device__ __nv_bfloat16 g_whi[4*D_*D_];   // Wq, Wk, Wv, Wo
__device__ __nv_bfloat16 g_wlo[4*D_*D_];
__device__ __nv_bfloat16 g_aohi[MSZ*D_];
__device__ __nv_bfloat16 g_aolo[MSZ*D_];

__device__ __nv_bfloat16 g_qhi[MSZ*D_];
__device__ __nv_bfloat16 g_qlo[MSZ*D_];
__device__ __nv_bfloat16 g_khi[MSZ*D_];
__device__ __nv_bfloat16 g_klo[MSZ*D_];
__device__ __nv_bfloat16 g_vthi[MSZ*D_];   // [B][H][64][S]
__device__ __nv_bfloat16 g_vtlo[MSZ*D_];

// ---------------------------------------------------------------------------
// fp32 -> bf16 (hi, lo) split
// ---------------------------------------------------------------------------
__global__ __launch_bounds__(256)
void convert_split(const float4* __restrict__ in,
                   uint2* __restrict__ hi, uint2* __restrict__ lo, int n4)
{
    int i = blockIdx.x * 256 + threadIdx.x;
    if (i >= n4) return;
    float4 v = in[i];
    __nv_bfloat162 h0 = __floats2bfloat162_rn(v.x, v.y);
    __nv_bfloat162 h1 = __floats2bfloat162_rn(v.z, v.w);
    __nv_bfloat162 l0 = __floats2bfloat162_rn(v.x - __bfloat162float(h0.x),
                                              v.y - __bfloat162float(h0.y));
    __nv_bfloat162 l1 = __floats2bfloat162_rn(v.z - __bfloat162float(h1.x),
                                              v.w - __bfloat162float(h1.y));
    uint2 H, L;
    H.x = *(const uint32_t*)&h0; H.y = *(const uint32_t*)&h1;
    L.x = *(const uint32_t*)&l0; L.y = *(const uint32_t*)&l1;
    hi[i] = H; lo[i] = L;
}

// ---------------------------------------------------------------------------
// V: [b, s, h*64+d] fp32  ->  VT hi/lo bf16 [b, h, d(64), s]
// ---------------------------------------------------------------------------
__global__ __launch_bounds__(256)
void transpose_split_v(const float* __restrict__ v,
                       __nv_bfloat16* __restrict__ vthi,
                       __nv_bfloat16* __restrict__ vtlo)
{
    __shared__ float tile[32][33];
    const int s0 = blockIdx.x * 32, d0 = blockIdx.y * 32, b = blockIdx.z;
    const int c = threadIdx.x & 31, r4 = threadIdx.x >> 5;
    #pragma unroll
    for (int i = 0; i < 4; i++) {
        int r = r4 + i * 8;
        tile[r][c] = v[(size_t)(b*S_ + s0 + r) * D_ + d0 + c];
    }
    __syncthreads();
    #pragma unroll
    for (int i = 0; i < 4; i++) {
        int d = d0 + r4 + i * 8;
        int s = s0 + c;
        float f = tile[c][r4 + i*8];
        __nv_bfloat16 hb = __float2bfloat16(f);
        float lo = f - __bfloat162float(hb);
        size_t o = ((size_t)(b*H_ + (d >> 6)) * 64 + (d & 63)) * S_ + s;
        vthi[o] = hb;
        vtlo[o] = __float2bfloat16(lo);
    }
}

// ---------------------------------------------------------------------------
// PTX helpers (non-variant ISA)
// ---------------------------------------------------------------------------
__device__ __forceinline__ uint32_t smem_u32(const void* p) {
    uint32_t a;
    asm("{ .reg .u64 t; cvta.to.shared.u64 t, %1; cvt.u32.u64 %0, t; }" : "=r"(a) : "l"(p));
    return a;
}
__device__ __forceinline__ void ldm_x4(uint32_t* r, uint32_t addr) {
    asm volatile("ldmatrix.sync.aligned.m8n8.x4.shared.b16 {%0,%1,%2,%3}, [%4];"
        : "=r"(r[0]), "=r"(r[1]), "=r"(r[2]), "=r"(r[3]) : "r"(addr));
}
__device__ __forceinline__ void ldm_x2(uint32_t* r, uint32_t addr) {
    asm volatile("ldmatrix.sync.aligned.m8n8.x2.shared.b16 {%0,%1}, [%2];"
        : "=r"(r[0]), "=r"(r[1]) : "r"(addr));
}
__device__ __forceinline__ void mma_bf16(float* c, const uint32_t* a,
                                         uint32_t b0, uint32_t b1) {
    asm volatile(
        "mma.sync.aligned.m16n8k16.row.col.f32.bf16.bf16.f32 "
        "{%0,%1,%2,%3}, {%4,%5,%6,%7}, {%8,%9}, {%0,%1,%2,%3};"
        : "+f"(c[0]), "+f"(c[1]), "+f"(c[2]), "+f"(c[3])
        : "r"(a[0]), "r"(a[1]), "r"(a[2]), "r"(a[3]), "r"(b0), "r"(b1));
}

// ---------------------------------------------------------------------------
// HMMA GEMM (unchanged, bench-proven): C = A @ W^T + bias, hi/lo 3-term.
// ---------------------------------------------------------------------------
#define LDT 40

__global__ __launch_bounds__(256)
void gemm_hmma(const __nv_bfloat16* __restrict__ Ahi, const __nv_bfloat16* __restrict__ Alo,
               const __nv_bfloat16* __restrict__ Bhi, const __nv_bfloat16* __restrict__ Blo,
               const float* __restrict__ bias, float* __restrict__ C,
               int M, int N, int K)
{
    __shared__ __nv_bfloat16 sA[2][128*LDT];
    __shared__ __nv_bfloat16 sB[2][128*LDT];

    const int tid = threadIdx.x;
    const int lane = tid & 31;
    const int wid  = tid >> 5;
    const int wm = wid & 1;
    const int wn = wid >> 1;
    const int m0 = blockIdx.y * 128;
    const int n0 = blockIdx.x * 128;

    const int sub = lane >> 3, rr = lane & 7;
    const int rowoff = ((sub & 1) << 3) + rr;
    const int koffb  = (sub >> 1) << 4;

    const uint32_t aHi = smem_u32(sA[0]) + (uint32_t)((wm*64 + rowoff) * (LDT*2) + koffb);
    const uint32_t aLo = smem_u32(sA[1]) + (uint32_t)((wm*64 + rowoff) * (LDT*2) + koffb);
    const uint32_t bHi = smem_u32(sB[0]) + (uint32_t)((wn*32 + rowoff) * (LDT*2) + koffb);
    const uint32_t bLo = smem_u32(sB[1]) + (uint32_t)((wn*32 + rowoff) * (LDT*2) + koffb);

    float acc[4][4][4];
    #pragma unroll
    for (int i = 0; i < 4; i++)
        #pragma unroll
        for (int j = 0; j < 4; j++)
            #pragma unroll
            for (int q = 0; q < 4; q++) acc[i][j][q] = 0.f;

    for (int k0 = 0; k0 < K; k0 += 32) {
        __syncthreads();
        #pragma unroll
        for (int buf = 0; buf < 4; buf++) {
            const __nv_bfloat16* g =
                (buf == 0) ? Ahi + (size_t)m0 * K :
                (buf == 1) ? Alo + (size_t)m0 * K :
                (buf == 2) ? Bhi + (size_t)n0 * K :
                             Blo + (size_t)n0 * K;
            __nv_bfloat16* s = (buf < 2) ? sA[buf] : sB[buf - 2];
            #pragma unroll
            for (int it = 0; it < 2; it++) {
                int idx = it * 256 + tid;
                int row = idx >> 2, vv = idx & 3;
                uint4 t = *(const uint4*)(g + (size_t)row * K + k0 + vv * 8);
                *(uint4*)(s + row * LDT + vv * 8) = t;
            }
        }
        __syncthreads();

        #pragma unroll
        for (int ks = 0; ks < 2; ks++) {
            const uint32_t kb = (uint32_t)(ks * 32);
            uint32_t ah[4][4], bh[2][4], bl[2][4];
            #pragma unroll
            for (int mt = 0; mt < 4; mt++) ldm_x4(ah[mt], aHi + mt * (16*LDT*2) + kb);
            ldm_x4(bh[0], bHi + kb);
            ldm_x4(bh[1], bHi + 16*LDT*2 + kb);
            ldm_x4(bl[0], bLo + kb);
            ldm_x4(bl[1], bLo + 16*LDT*2 + kb);

            #pragma unroll
            for (int mt = 0; mt < 4; mt++)
                #pragma unroll
                for (int nf = 0; nf < 4; nf++) {
                    const int nb = nf >> 1, sel = nf & 1;
                    mma_bf16(acc[mt][nf], ah[mt], bh[nb][sel], bh[nb][2+sel]);
                    mma_bf16(acc[mt][nf], ah[mt], bl[nb][sel], bl[nb][2+sel]);
                }

            uint32_t al[4][4];
            #pragma unroll
            for (int mt = 0; mt < 4; mt++) ldm_x4(al[mt], aLo + mt * (16*LDT*2) + kb);
            #pragma unroll
            for (int mt = 0; mt < 4; mt++)
                #pragma unroll
                for (int nf = 0; nf < 4; nf++) {
                    const int nb = nf >> 1, sel = nf & 1;
                    mma_bf16(acc[mt][nf], al[mt], bh[nb][sel], bh[nb][2+sel]);
                }
        }
    }

    const int g = lane >> 2, t = lane & 3;
    #pragma unroll
    for (int mt = 0; mt < 4; mt++) {
        const int row = m0 + wm*64 + mt*16 + g;
        #pragma unroll
        for (int nf = 0; nf < 4; nf++) {
            const int col = n0 + wn*32 + nf*8 + t*2;
            const float b0 = bias[col], b1 = bias[col+1];
            float2 lo2 = { acc[mt][nf][0] + b0, acc[mt][nf][1] + b1 };
            float2 hi2 = { acc[mt][nf][2] + b0, acc[mt][nf][3] + b1 };
            *(float2*)(C + (size_t)row * N + col)       = lo2;
            *(float2*)(C + (size_t)(row + 8) * N + col) = hi2;
        }
    }
}

// ---------------------------------------------------------------------------
// HMMA fused causal attention. TQ=16 queries/CTA, 512 threads (16 warps).
// Scores & AV on tensor cores (bf16 hi/lo 3-term), exact softmax in smem.
// smem layout (bytes):
//   [0, 131072)           rows:  fp32 [16][2048]
//   [131072, 204800)      K chunk hi/lo [256][72] bf16  (phase 4: VT [64][264] x2)
//   [204800, 221696)      P chunk hi/lo [16][264] bf16
//   [221696, 226304)      Q hi/lo [16][72] bf16         (phase 4 tail: pbuf fp32)
// ---------------------------------------------------------------------------
#define KST 72     // K/Q smem stride (bf16): 144B rows -> conflict-free ldmatrix
#define VST 264    // VT/P smem stride (bf16): 528B rows -> conflict-free

#define OFF_KV 131072
#define OFF_P  204800
#define OFF_Q  221696
#define SM_ATT 226304

__global__ __launch_bounds__(512)
void attn_hmma(const __nv_bfloat16* __restrict__ qhi, const __nv_bfloat16* __restrict__ qlo,
               const __nv_bfloat16* __restrict__ khi, const __nv_bfloat16* __restrict__ klo,
               const __nv_bfloat16* __restrict__ vthi, const __nv_bfloat16* __restrict__ vtlo,
               float* __restrict__ attnw, float* __restrict__ AO)
{
    extern __shared__ char smb[];
    float* rows = (float*)smb;
    __nv_bfloat16* Khi = (__nv_bfloat16*)(smb + OFF_KV);
    __nv_bfloat16* Klo = Khi + 256*KST;
    __nv_bfloat16* VThi = (__nv_bfloat16*)(smb + OFF_KV);
    __nv_bfloat16* VTlo = VThi + 64*VST;
    __nv_bfloat16* Phi = (__nv_bfloat16*)(smb + OFF_P);
    __nv_bfloat16* Plo = Phi + 16*VST;
    __nv_bfloat16* Qhi = (__nv_bfloat16*)(smb + OFF_Q);
    __nv_bfloat16* Qlo = Qhi + 16*KST;
    float* pbuf = (float*)(smb + OFF_Q);    // reused after phase 1/2

    const int qt = blockIdx.x, h = blockIdx.y, b = blockIdx.z;
    const int q0 = qt * TQ;
    const int tid  = threadIdx.x;
    const int lane = tid & 31;
    const int wid  = tid >> 5;
    const int nk   = q0 + TQ;
    const int nChunk = (nk + KCA - 1) / KCA;
    const int nkc = nChunk * KCA;
    const float scale = 0.125f;

    // A/B fragment lane addressing (bench-proven pattern from gemm_hmma)
    const int sub = lane >> 3, rr = lane & 7;
    const int arow = ((sub & 1) << 3) + rr;     // 0..15
    const int akoff = (sub >> 1) << 4;          // 0 or 16 bytes

    // ---- load Q tile (hi/lo) into smem ----
    {
        const size_t qgb = ((size_t)(b*S_ + q0)) * D_ + h*HD_;
        for (int i = tid; i < 256; i += 512) {
            int which = i >> 7, u = i & 127;
            int token = u >> 3, seg = u & 7;
            const __nv_bfloat16* src = (which ? qlo : qhi) + qgb + (size_t)token * D_ + seg*8;
            __nv_bfloat16* dst = (which ? Qlo : Qhi) + token*KST + seg*8;
            *(uint4*)dst = *(const uint4*)src;
        }
    }
    __syncthreads();

    // preload Q fragments (constant over chunks)
    uint32_t qfh[4][4], qfl[4][4];
    {
        const uint32_t qa_hi = smem_u32(Qhi) + (uint32_t)(arow*(KST*2) + akoff);
        const uint32_t qa_lo = smem_u32(Qlo) + (uint32_t)(arow*(KST*2) + akoff);
        #pragma unroll
        for (int ks = 0; ks < 4; ks++) {
            ldm_x4(qfh[ks], qa_hi + ks*32);
            ldm_x4(qfl[ks], qa_lo + ks*32);
        }
    }

    // ---- Phase 1: scores via HMMA; warp w handles keys [w*16, w*16+16) ----
    const uint32_t kB_hi = smem_u32(Khi) + (uint32_t)((wid*16 + arow)*(KST*2) + akoff);
    const uint32_t kB_lo = smem_u32(Klo) + (uint32_t)((wid*16 + arow)*(KST*2) + akoff);
    const int gq = lane >> 2, t2 = (lane & 3) << 1;
    const size_t kgb = ((size_t)b*S_) * D_ + h*HD_;

    for (int c = 0; c < nChunk; c++) {
        const int k0c = c * KCA;
        __syncthreads();
        #pragma unroll
        for (int it = 0; it < 8; it++) {
            int u = tid + it * 512;
            int which = u >> 11, uu = u & 2047;
            int token = uu >> 3, seg = uu & 7;
            const __nv_bfloat16* src = (which ? klo : khi) + kgb
                + (size_t)(k0c + token) * D_ + seg*8;
            __nv_bfloat16* dst = (which ? Klo : Khi) + token*KST + seg*8;
            *(uint4*)dst = *(const uint4*)src;
        }
        __syncthreads();

        float sc[2][4];
        #pragma unroll
        for (int ns = 0; ns < 2; ns++)
            #pragma unroll
            for (int j = 0; j < 4; j++) sc[ns][j] = 0.f;

        #pragma unroll
        for (int ks = 0; ks < 4; ks++) {
            uint32_t kh[4], kl[4];
            ldm_x4(kh, kB_hi + ks*32);
            ldm_x4(kl, kB_lo + ks*32);
            #pragma unroll
            for (int ns = 0; ns < 2; ns++) {
                mma_bf16(sc[ns], qfh[ks], kh[ns], kh[2+ns]);
                mma_bf16(sc[ns], qfh[ks], kl[ns], kl[2+ns]);
                mma_bf16(sc[ns], qfl[ks], kh[ns], kh[2+ns]);
            }
        }

        #pragma unroll
        for (int ns = 0; ns < 2; ns++) {
            const int kg = k0c + wid*16 + ns*8 + t2;
            rows[(size_t)gq*S_ + kg]      = (kg   <= q0+gq) ? sc[ns][0]*scale : -INFINITY;
            rows[(size_t)gq*S_ + kg+1]    = (kg+1 <= q0+gq) ? sc[ns][1]*scale : -INFINITY;
            rows[(size_t)(gq+8)*S_ + kg]  = (kg   <= q0+gq+8) ? sc[ns][2]*scale : -INFINITY;
            rows[(size_t)(gq+8)*S_ + kg+1]= (kg+1 <= q0+gq+8) ? sc[ns][3]*scale : -INFINITY;
        }
    }
    __syncthreads();

    // ---- Phase 2: exact softmax, one warp per row ----
    {
        const int r = wid;
        float* prow = rows + (size_t)r * S_;
        float m = -INFINITY;
        for (int i = lane; i < nkc; i += 32) m = fmaxf(m, prow[i]);
        #pragma unroll
        for (int off = 16; off; off >>= 1) m = fmaxf(m, __shfl_xor_sync(0xffffffffu, m, off));
        float s = 0.f;
        for (int i = lane; i < nkc; i += 32) {
            float e = __expf(prow[i] - m);
            prow[i] = e;
            s += e;
        }
        #pragma unroll
        for (int off = 16; off; off >>= 1) s += __shfl_xor_sync(0xffffffffu, s, off);
        float inv = 1.f / s;
        for (int i = lane; i < nkc; i += 32) prow[i] *= inv;
    }
    __syncthreads();

    // ---- Phase 3: write normalized attn_weights ----
    {
        size_t abase = (((size_t)b * H_ + h) * S_ + q0) * (size_t)S_;
        for (int i = tid; i < TQ * S_; i += 512) {
            int r   = i >> 11;
            int col = i & (S_ - 1);
            float v = 0.f;
            if (col <= q0 + r) v = rows[(size_t)r * S_ + col];
            attnw[abase + (size_t)r * S_ + col] = v;
        }
    }

    // ---- Phase 4: AV via HMMA. warp = (khalf = wid>>3, ntile = wid&7) ----
    const int khalf = wid >> 3, ntile = wid & 7;
    const uint32_t pA_hi = smem_u32(Phi) + (uint32_t)(arow*(VST*2) + akoff + khalf*256);
    const uint32_t pA_lo = smem_u32(Plo) + (uint32_t)(arow*(VST*2) + akoff + khalf*256);
    const uint32_t vB_hi = smem_u32(VThi) + (uint32_t)((ntile*8 + rr)*(VST*2)
                          + (((lane >> 3) & 1) << 4) + khalf*256);
    const uint32_t vB_lo = vB_hi + (uint32_t)(64*VST*2);
    const size_t vgb = ((size_t)(b*H_ + h)) * 64 * S_;

    float oc[4] = {0.f, 0.f, 0.f, 0.f};
    for (int c = 0; c < nChunk; c++) {
        const int k0c = c * KCA;
        __syncthreads();
        // load VT chunk hi/lo: [64 dims][256 keys]
        #pragma unroll
        for (int it = 0; it < 8; it++) {
            int u = tid + it * 512;
            int which = u >> 11, uu = u & 2047;
            int d = uu >> 5, seg = uu & 31;
            const __nv_bfloat16* src = (which ? vtlo : vthi) + vgb
                + (size_t)d * S_ + k0c + seg*8;
            __nv_bfloat16* dst = (which ? VTlo : VThi) + d*VST + seg*8;
            *(uint4*)dst = *(const uint4*)src;
        }
        // convert P chunk fp32 -> bf16 hi/lo
        #pragma unroll
        for (int it = 0; it < 4; it++) {
            int p = tid + it * 512;           // 2048 pairs
            int r = p >> 7, j2 = (p & 127) << 1;
            float v0 = rows[(size_t)r*S_ + k0c + j2];
            float v1 = rows[(size_t)r*S_ + k0c + j2 + 1];
            __nv_bfloat162 hb = __floats2bfloat162_rn(v0, v1);
            __nv_bfloat162 lb = __floats2bfloat162_rn(v0 - __bfloat162float(hb.x),
                                                      v1 - __bfloat162float(hb.y));
            *(uint32_t*)(Phi + r*VST + j2) = *(const uint32_t*)&hb;
            *(uint32_t*)(Plo + r*VST + j2) = *(const uint32_t*)&lb;
        }
        __syncthreads();

        #pragma unroll
        for (int ks = 0; ks < 8; ks++) {
            uint32_t ph[4], pl[4], vh[2], vl[2];
            ldm_x4(ph, pA_hi + ks*32);
            ldm_x4(pl, pA_lo + ks*32);
            ldm_x2(vh, vB_hi + ks*32);
            ldm_x2(vl, vB_lo + ks*32);
            mma_bf16(oc, ph, vh[0], vh[1]);
            mma_bf16(oc, ph, vl[0], vl[1]);
            mma_bf16(oc, pl, vh[0], vh[1]);
        }
    }

    // combine k-halves via pbuf (reuses Q smem region)
    __syncthreads();
    if (khalf == 1) {
        pbuf[gq*HD_ + ntile*8 + t2]       = oc[0];
        pbuf[gq*HD_ + ntile*8 + t2 + 1]   = oc[1];
        pbuf[(gq+8)*HD_ + ntile*8 + t2]   = oc[2];
        pbuf[(gq+8)*HD_ + ntile*8 + t2+1] = oc[3];
    }
    __syncthreads();
    if (khalf == 0) {
        const int col = h*HD_ + ntile*8 + t2;
        float* r0p = AO + ((size_t)(b*S_ + q0 + gq)) * D_ + col;
        float* r1p = AO + ((size_t)(b*S_ + q0 + gq + 8)) * D_ + col;
        float2 a0 = { oc[0] + pbuf[gq*HD_ + ntile*8 + t2],
                      oc[1] + pbuf[gq*HD_ + ntile*8 + t2 + 1] };
        float2 a1 = { oc[2] + pbuf[(gq+8)*HD_ + ntile*8 + t2],
                      oc[3] + pbuf[(gq+8)*HD_ + ntile*8 + t2 + 1] };
        *(float2*)r0p = a0;
        *(float2*)r1p = a1;
    }
}

// ---------------------------------------------------------------------------
extern "C" void kernel_launch(void* const* d_in, const int* in_sizes, int n_in,
                              void* d_out, int out_size)
{
    const float* x  = (const float*)d_in[0];
    const float* Wq = (const float*)d_in[1];
    const float* bq = (const float*)d_in[2];
    const float* Wk = (const float*)d_in[3];
    const float* bk = (const float*)d_in[4];
    const float* Wv = (const float*)d_in[5];
    const float* bv = (const float*)d_in[6];
    const float* Wo = (const float*)d_in[7];
    const float* bo = (const float*)d_in[8];

    float* out   = (float*)d_out;                       // [B,S,D]
    float* attnw = out + (size_t)B_ * S_ * D_;          // [B,H,S,S]

    float *q, *k, *v, *ao;
    __nv_bfloat16 *xhi, *xlo, *whi, *wlo, *aohi, *aolo;
    __nv_bfloat16 *qhi, *qlo, *khi, *klo, *vthi, *vtlo;
    cudaGetSymbolAddress((void**)&q,  g_q);
    cudaGetSymbolAddress((void**)&k,  g_k);
    cudaGetSymbolAddress((void**)&v,  g_v);
    cudaGetSymbolAddress((void**)&ao, g_ao);
    cudaGetSymbolAddress((void**)&xhi, g_xhi);
    cudaGetSymbolAddress((void**)&xlo, g_xlo);
    cudaGetSymbolAddress((void**)&whi, g_whi);
    cudaGetSymbolAddress((void**)&wlo, g_wlo);
    cudaGetSymbolAddress((void**)&aohi, g_aohi);
    cudaGetSymbolAddress((void**)&aolo, g_aolo);
    cudaGetSymbolAddress((void**)&qhi, g_qhi);
    cudaGetSymbolAddress((void**)&qlo, g_qlo);
    cudaGetSymbolAddress((void**)&khi, g_khi);
    cudaGetSymbolAddress((void**)&klo, g_klo);
    cudaGetSymbolAddress((void**)&vthi, g_vthi);
    cudaGetSymbolAddress((void**)&vtlo, g_vtlo);

    const int M = MSZ;               // 4096
    const int WSZ = D_ * D_;         // 1048576
    const int NPX = M * D_ / 4;      // float4 count

    convert_split<<<(NPX + 255)/256, 256>>>((const float4*)x, (uint2*)xhi, (uint2*)xlo, NPX);
    const float* Ws[4] = { Wq, Wk, Wv, Wo };
    for (int i = 0; i < 4; i++)
        convert_split<<<(WSZ/4 + 255)/256, 256>>>((const float4*)Ws[i],
            (uint2*)(whi + (size_t)i*WSZ), (uint2*)(wlo + (size_t)i*WSZ), WSZ/4);

    dim3 ggrid(D_ / 128, M / 128);   // (8, 32)
    gemm_hmma<<<ggrid, 256>>>(xhi, xlo, whi + 0*(size_t)WSZ, wlo + 0*(size_t)WSZ, bq, q, M, D_, D_);
    gemm_hmma<<<ggrid, 256>>>(xhi, xlo, whi + 1*(size_t)WSZ, wlo + 1*(size_t)WSZ, bk, k, M, D_, D_);
    gemm_hmma<<<ggrid, 256>>>(xhi, xlo, whi + 2*(size_t)WSZ, wlo + 2*(size_t)WSZ, bv, v, M, D_, D_);

    // split q/k, transpose+split v
    convert_split<<<(NPX + 255)/256, 256>>>((const float4*)q, (uint2*)qhi, (uint2*)qlo, NPX);
    convert_split<<<(NPX + 255)/256, 256>>>((const float4*)k, (uint2*)khi, (uint2*)klo, NPX);
    {
        dim3 tg(S_/32, D_/32, B_);
        transpose_split_v<<<tg, 256>>>(v, vthi, vtlo);
    }

    cudaFuncSetAttribute(attn_hmma, cudaFuncAttributeMaxDynamicSharedMemorySize, SM_ATT);
    dim3 attn_grid(S_ / TQ, H_, B_);
    attn_hmma<<<attn_grid, 512, SM_ATT>>>(qhi, qlo, khi, klo, vthi, vtlo, attnw, ao);

    convert_split<<<(NPX + 255)/256, 256>>>((const float4*)ao, (uint2*)aohi, (uint2*)aolo, NPX);
    gemm_hmma<<<ggrid, 256>>>(aohi, aolo, whi + 3*(size_t)WSZ, wlo + 3*(size_t)WSZ, bo, out, M, D_, D_);
}

// round 7
// speedup vs baseline: 3.3632x; 1.1299x over previous
#include <cuda_runtime.h>
#include <cuda_bf16.h>
#include <math.h>
#include <stdint.h>

#define B_  2
#define S_  2048
#define D_  1024
#define H_  16
#define HD_ 64

#define TQ  16
#define KCA 256              // attention key-chunk

#define MSZ (B_*S_)          // 4096 rows

// ---------------------------------------------------------------------------
// Scratch (allocation-free rule: __device__ globals)
// ---------------------------------------------------------------------------
__device__ float g_q [B_*S_*D_];
__device__ float g_k [B_*S_*D_];
__device__ float g_v [B_*S_*D_];

__device__ __nv_bfloat16 g_xhi[MSZ*D_];
__device__ __nv_bfloat16 g_xlo[MSZ*D_];
__device__ __nv_bfloat16 g_whi[4*D_*D_];   // Wq, Wk, Wv, Wo
__device__ __nv_bfloat16 g_wlo[4*D_*D_];
__device__ __nv_bfloat16 g_aohi[MSZ*D_];
__device__ __nv_bfloat16 g_aolo[MSZ*D_];

__device__ __nv_bfloat16 g_qhi[MSZ*D_];
__device__ __nv_bfloat16 g_qlo[MSZ*D_];
__device__ __nv_bfloat16 g_khi[MSZ*D_];
__device__ __nv_bfloat16 g_klo[MSZ*D_];
__device__ __nv_bfloat16 g_vthi[MSZ*D_];   // [B][H][64][S]
__device__ __nv_bfloat16 g_vtlo[MSZ*D_];

// ---------------------------------------------------------------------------
// fp32 -> bf16 (hi, lo) split
// ---------------------------------------------------------------------------
__global__ __launch_bounds__(256)
void convert_split(const float4* __restrict__ in,
                   uint2* __restrict__ hi, uint2* __restrict__ lo, int n4)
{
    int i = blockIdx.x * 256 + threadIdx.x;
    if (i >= n4) return;
    float4 v = in[i];
    __nv_bfloat162 h0 = __floats2bfloat162_rn(v.x, v.y);
    __nv_bfloat162 h1 = __floats2bfloat162_rn(v.z, v.w);
    __nv_bfloat162 l0 = __floats2bfloat162_rn(v.x - __bfloat162float(h0.x),
                                              v.y - __bfloat162float(h0.y));
    __nv_bfloat162 l1 = __floats2bfloat162_rn(v.z - __bfloat162float(h1.x),
                                              v.w - __bfloat162float(h1.y));
    uint2 H, L;
    H.x = *(const uint32_t*)&h0; H.y = *(const uint32_t*)&h1;
    L.x = *(const uint32_t*)&l0; L.y = *(const uint32_t*)&l1;
    hi[i] = H; lo[i] = L;
}

// ---------------------------------------------------------------------------
// V: [b, s, h*64+d] fp32  ->  VT hi/lo bf16 [b, h, d(64), s]
// ---------------------------------------------------------------------------
__global__ __launch_bounds__(256)
void transpose_split_v(const float* __restrict__ v,
                       __nv_bfloat16* __restrict__ vthi,
                       __nv_bfloat16* __restrict__ vtlo)
{
    __shared__ float tile[32][33];
    const int s0 = blockIdx.x * 32, d0 = blockIdx.y * 32, b = blockIdx.z;
    const int c = threadIdx.x & 31, r4 = threadIdx.x >> 5;
    #pragma unroll
    for (int i = 0; i < 4; i++) {
        int r = r4 + i * 8;
        tile[r][c] = v[(size_t)(b*S_ + s0 + r) * D_ + d0 + c];
    }
    __syncthreads();
    #pragma unroll
    for (int i = 0; i < 4; i++) {
        int d = d0 + r4 + i * 8;
        int s = s0 + c;
        float f = tile[c][r4 + i*8];
        __nv_bfloat16 hb = __float2bfloat16(f);
        float lo = f - __bfloat162float(hb);
        size_t o = ((size_t)(b*H_ + (d >> 6)) * 64 + (d & 63)) * S_ + s;
        vthi[o] = hb;
        vtlo[o] = __float2bfloat16(lo);
    }
}

// ---------------------------------------------------------------------------
// PTX helpers (non-variant ISA)
// ---------------------------------------------------------------------------
__device__ __forceinline__ uint32_t smem_u32(const void* p) {
    uint32_t a;
    asm("{ .reg .u64 t; cvta.to.shared.u64 t, %1; cvt.u32.u64 %0, t; }" : "=r"(a) : "l"(p));
    return a;
}
__device__ __forceinline__ void ldm_x4(uint32_t* r, uint32_t addr) {
    asm volatile("ldmatrix.sync.aligned.m8n8.x4.shared.b16 {%0,%1,%2,%3}, [%4];"
        : "=r"(r[0]), "=r"(r[1]), "=r"(r[2]), "=r"(r[3]) : "r"(addr));
}
__device__ __forceinline__ void ldm_x2(uint32_t* r, uint32_t addr) {
    asm volatile("ldmatrix.sync.aligned.m8n8.x2.shared.b16 {%0,%1}, [%2];"
        : "=r"(r[0]), "=r"(r[1]) : "r"(addr));
}
__device__ __forceinline__ void mma_bf16(float* c, const uint32_t* a,
                                         uint32_t b0, uint32_t b1) {
    asm volatile(
        "mma.sync.aligned.m16n8k16.row.col.f32.bf16.bf16.f32 "
        "{%0,%1,%2,%3}, {%4,%5,%6,%7}, {%8,%9}, {%0,%1,%2,%3};"
        : "+f"(c[0]), "+f"(c[1]), "+f"(c[2]), "+f"(c[3])
        : "r"(a[0]), "r"(a[1]), "r"(a[2]), "r"(a[3]), "r"(b0), "r"(b1));
}
__device__ __forceinline__ void cp16(uint32_t dst, const void* src) {
    asm volatile("cp.async.cg.shared.global [%0], [%1], 16;" :: "r"(dst), "l"(src));
}
#define CP_COMMIT() asm volatile("cp.async.commit_group;" ::: "memory")
#define CP_WAIT0()  asm volatile("cp.async.wait_group 0;" ::: "memory")

// ---------------------------------------------------------------------------
// HMMA GEMM: C = A @ W^T + bias, hi/lo 3-term, cp.async 2-stage pipeline.
// 128x128 tile/CTA, K-chunks of 32, 8 warps, 2 CTAs/SM.
// Dynamic smem: 2 stages x 4 tiles (Ahi,Alo,Bhi,Blo) x [128][LDT] bf16.
// If Chi != null: write bf16 hi/lo split instead of fp32 C.
// ---------------------------------------------------------------------------
#define LDT 40
#define TILE_B   (128*LDT*2)         // 10240 bytes per tile
#define STAGE_B  (4*TILE_B)          // 40960 bytes per stage
#define SM_GEMM  (2*STAGE_B)         // 81920 bytes

__global__ __launch_bounds__(256, 2)
void gemm_hmma(const __nv_bfloat16* __restrict__ Ahi, const __nv_bfloat16* __restrict__ Alo,
               const __nv_bfloat16* __restrict__ Bhi, const __nv_bfloat16* __restrict__ Blo,
               const float* __restrict__ bias, float* __restrict__ C,
               __nv_bfloat16* __restrict__ Chi, __nv_bfloat16* __restrict__ Clo,
               int M, int N, int K)
{
    extern __shared__ __nv_bfloat16 dsm[];
    const uint32_t sb = smem_u32(dsm);

    const int tid = threadIdx.x;
    const int lane = tid & 31;
    const int wid  = tid >> 5;
    const int wm = wid & 1;
    const int wn = wid >> 1;
    const int m0 = blockIdx.y * 128;
    const int n0 = blockIdx.x * 128;

    const int sub = lane >> 3, rr = lane & 7;
    const int rowoff = ((sub & 1) << 3) + rr;
    const int koffb  = (sub >> 1) << 4;

    // per-thread fragment byte offsets within a stage
    const uint32_t offA = (uint32_t)((wm*64 + rowoff) * (LDT*2) + koffb);
    const uint32_t offB = (uint32_t)((wn*32 + rowoff) * (LDT*2) + koffb);

    // cp.async per-thread source/dest (2 vec16 per tile per thread)
    const int crow0 = tid >> 2, cvv = tid & 3;          // rows 0..63
    const __nv_bfloat16* gsrc[4] = {
        Ahi + (size_t)m0 * K, Alo + (size_t)m0 * K,
        Bhi + (size_t)n0 * K, Blo + (size_t)n0 * K };

    float acc[4][4][4];
    #pragma unroll
    for (int i = 0; i < 4; i++)
        #pragma unroll
        for (int j = 0; j < 4; j++)
            #pragma unroll
            for (int q = 0; q < 4; q++) acc[i][j][q] = 0.f;

    const int nChunk = K / 32;

    // prologue: issue chunk 0 into stage 0
    #pragma unroll
    for (int t = 0; t < 4; t++) {
        #pragma unroll
        for (int it = 0; it < 2; it++) {
            int row = crow0 + it * 64;
            cp16(sb + (uint32_t)(t*TILE_B + row*(LDT*2) + cvv*16),
                 gsrc[t] + (size_t)row * K + cvv*8);
        }
    }
    CP_COMMIT();

    int buf = 0;
    for (int c = 0; c < nChunk; c++) {
        CP_WAIT0();
        __syncthreads();

        if (c + 1 < nChunk) {
            const int k1 = (c + 1) * 32;
            const uint32_t stg = (uint32_t)((buf ^ 1) * STAGE_B);
            #pragma unroll
            for (int t = 0; t < 4; t++) {
                #pragma unroll
                for (int it = 0; it < 2; it++) {
                    int row = crow0 + it * 64;
                    cp16(sb + stg + (uint32_t)(t*TILE_B + row*(LDT*2) + cvv*16),
                         gsrc[t] + (size_t)row * K + k1 + cvv*8);
                }
            }
            CP_COMMIT();
        }

        const uint32_t stg = (uint32_t)(buf * STAGE_B);
        const uint32_t aHi = sb + stg + offA;
        const uint32_t aLo = aHi + TILE_B;
        const uint32_t bHi = sb + stg + 2*TILE_B + offB;
        const uint32_t bLo = bHi + TILE_B;

        #pragma unroll
        for (int ks = 0; ks < 2; ks++) {
            const uint32_t kb = (uint32_t)(ks * 32);
            uint32_t ah[4][4], bh[2][4], bl[2][4];
            #pragma unroll
            for (int mt = 0; mt < 4; mt++) ldm_x4(ah[mt], aHi + mt * (16*LDT*2) + kb);
            ldm_x4(bh[0], bHi + kb);
            ldm_x4(bh[1], bHi + 16*LDT*2 + kb);
            ldm_x4(bl[0], bLo + kb);
            ldm_x4(bl[1], bLo + 16*LDT*2 + kb);

            #pragma unroll
            for (int mt = 0; mt < 4; mt++)
                #pragma unroll
                for (int nf = 0; nf < 4; nf++) {
                    const int nb = nf >> 1, sel = nf & 1;
                    mma_bf16(acc[mt][nf], ah[mt], bh[nb][sel], bh[nb][2+sel]);
                    mma_bf16(acc[mt][nf], ah[mt], bl[nb][sel], bl[nb][2+sel]);
                }

            uint32_t al[4][4];
            #pragma unroll
            for (int mt = 0; mt < 4; mt++) ldm_x4(al[mt], aLo + mt * (16*LDT*2) + kb);
            #pragma unroll
            for (int mt = 0; mt < 4; mt++)
                #pragma unroll
                for (int nf = 0; nf < 4; nf++) {
                    const int nb = nf >> 1, sel = nf & 1;
                    mma_bf16(acc[mt][nf], al[mt], bh[nb][sel], bh[nb][2+sel]);
                }
        }
        buf ^= 1;
    }

    const int g = lane >> 2, t = lane & 3;
    #pragma unroll
    for (int mt = 0; mt < 4; mt++) {
        const int row = m0 + wm*64 + mt*16 + g;
        #pragma unroll
        for (int nf = 0; nf < 4; nf++) {
            const int col = n0 + wn*32 + nf*8 + t*2;
            const float b0 = bias[col], b1 = bias[col+1];
            float v00 = acc[mt][nf][0] + b0, v01 = acc[mt][nf][1] + b1;
            float v10 = acc[mt][nf][2] + b0, v11 = acc[mt][nf][3] + b1;
            if (Chi) {
                __nv_bfloat162 h0 = __floats2bfloat162_rn(v00, v01);
                __nv_bfloat162 l0 = __floats2bfloat162_rn(v00 - __bfloat162float(h0.x),
                                                          v01 - __bfloat162float(h0.y));
                __nv_bfloat162 h1 = __floats2bfloat162_rn(v10, v11);
                __nv_bfloat162 l1 = __floats2bfloat162_rn(v10 - __bfloat162float(h1.x),
                                                          v11 - __bfloat162float(h1.y));
                *(uint32_t*)(Chi + (size_t)row * N + col)       = *(const uint32_t*)&h0;
                *(uint32_t*)(Clo + (size_t)row * N + col)       = *(const uint32_t*)&l0;
                *(uint32_t*)(Chi + (size_t)(row + 8) * N + col) = *(const uint32_t*)&h1;
                *(uint32_t*)(Clo + (size_t)(row + 8) * N + col) = *(const uint32_t*)&l1;
            } else {
                float2 lo2 = { v00, v01 };
                float2 hi2 = { v10, v11 };
                *(float2*)(C + (size_t)row * N + col)       = lo2;
                *(float2*)(C + (size_t)(row + 8) * N + col) = hi2;
            }
        }
    }
}

// ---------------------------------------------------------------------------
// HMMA fused causal attention (bench-proven R6 structure).
// Final output written directly as bf16 hi/lo (aohi/aolo).
// ---------------------------------------------------------------------------
#define KST 72
#define VST 264

#define OFF_KV 131072
#define OFF_P  204800
#define OFF_Q  221696
#define SM_ATT 226304

__global__ __launch_bounds__(512)
void attn_hmma(const __nv_bfloat16* __restrict__ qhi, const __nv_bfloat16* __restrict__ qlo,
               const __nv_bfloat16* __restrict__ khi, const __nv_bfloat16* __restrict__ klo,
               const __nv_bfloat16* __restrict__ vthi, const __nv_bfloat16* __restrict__ vtlo,
               float* __restrict__ attnw,
               __nv_bfloat16* __restrict__ aohi, __nv_bfloat16* __restrict__ aolo)
{
    extern __shared__ char smb[];
    float* rows = (float*)smb;
    __nv_bfloat16* Khi = (__nv_bfloat16*)(smb + OFF_KV);
    __nv_bfloat16* Klo = Khi + 256*KST;
    __nv_bfloat16* VThi = (__nv_bfloat16*)(smb + OFF_KV);
    __nv_bfloat16* VTlo = VThi + 64*VST;
    __nv_bfloat16* Phi = (__nv_bfloat16*)(smb + OFF_P);
    __nv_bfloat16* Plo = Phi + 16*VST;
    __nv_bfloat16* Qhi = (__nv_bfloat16*)(smb + OFF_Q);
    __nv_bfloat16* Qlo = Qhi + 16*KST;
    float* pbuf = (float*)(smb + OFF_Q);

    const int qt = blockIdx.x, h = blockIdx.y, b = blockIdx.z;
    const int q0 = qt * TQ;
    const int tid  = threadIdx.x;
    const int lane = tid & 31;
    const int wid  = tid >> 5;
    const int nk   = q0 + TQ;
    const int nChunk = (nk + KCA - 1) / KCA;
    const int nkc = nChunk * KCA;
    const float scale = 0.125f;

    const int sub = lane >> 3, rr = lane & 7;
    const int arow = ((sub & 1) << 3) + rr;
    const int akoff = (sub >> 1) << 4;

    {
        const size_t qgb = ((size_t)(b*S_ + q0)) * D_ + h*HD_;
        for (int i = tid; i < 256; i += 512) {
            int which = i >> 7, u = i & 127;
            int token = u >> 3, seg = u & 7;
            const __nv_bfloat16* src = (which ? qlo : qhi) + qgb + (size_t)token * D_ + seg*8;
            __nv_bfloat16* dst = (which ? Qlo : Qhi) + token*KST + seg*8;
            *(uint4*)dst = *(const uint4*)src;
        }
    }
    __syncthreads();

    uint32_t qfh[4][4], qfl[4][4];
    {
        const uint32_t qa_hi = smem_u32(Qhi) + (uint32_t)(arow*(KST*2) + akoff);
        const uint32_t qa_lo = smem_u32(Qlo) + (uint32_t)(arow*(KST*2) + akoff);
        #pragma unroll
        for (int ks = 0; ks < 4; ks++) {
            ldm_x4(qfh[ks], qa_hi + ks*32);
            ldm_x4(qfl[ks], qa_lo + ks*32);
        }
    }

    const uint32_t kB_hi = smem_u32(Khi) + (uint32_t)((wid*16 + arow)*(KST*2) + akoff);
    const uint32_t kB_lo = smem_u32(Klo) + (uint32_t)((wid*16 + arow)*(KST*2) + akoff);
    const int gq = lane >> 2, t2 = (lane & 3) << 1;
    const size_t kgb = ((size_t)b*S_) * D_ + h*HD_;

    for (int c = 0; c < nChunk; c++) {
        const int k0c = c * KCA;
        __syncthreads();
        #pragma unroll
        for (int it = 0; it < 8; it++) {
            int u = tid + it * 512;
            int which = u >> 11, uu = u & 2047;
            int token = uu >> 3, seg = uu & 7;
            const __nv_bfloat16* src = (which ? klo : khi) + kgb
                + (size_t)(k0c + token) * D_ + seg*8;
            __nv_bfloat16* dst = (which ? Klo : Khi) + token*KST + seg*8;
            *(uint4*)dst = *(const uint4*)src;
        }
        __syncthreads();

        float sc[2][4];
        #pragma unroll
        for (int ns = 0; ns < 2; ns++)
            #pragma unroll
            for (int j = 0; j < 4; j++) sc[ns][j] = 0.f;

        #pragma unroll
        for (int ks = 0; ks < 4; ks++) {
            uint32_t kh[4], kl[4];
            ldm_x4(kh, kB_hi + ks*32);
            ldm_x4(kl, kB_lo + ks*32);
            #pragma unroll
            for (int ns = 0; ns < 2; ns++) {
                mma_bf16(sc[ns], qfh[ks], kh[ns], kh[2+ns]);
                mma_bf16(sc[ns], qfh[ks], kl[ns], kl[2+ns]);
                mma_bf16(sc[ns], qfl[ks], kh[ns], kh[2+ns]);
            }
        }

        #pragma unroll
        for (int ns = 0; ns < 2; ns++) {
            const int kg = k0c + wid*16 + ns*8 + t2;
            rows[(size_t)gq*S_ + kg]      = (kg   <= q0+gq) ? sc[ns][0]*scale : -INFINITY;
            rows[(size_t)gq*S_ + kg+1]    = (kg+1 <= q0+gq) ? sc[ns][1]*scale : -INFINITY;
            rows[(size_t)(gq+8)*S_ + kg]  = (kg   <= q0+gq+8) ? sc[ns][2]*scale : -INFINITY;
            rows[(size_t)(gq+8)*S_ + kg+1]= (kg+1 <= q0+gq+8) ? sc[ns][3]*scale : -INFINITY;
        }
    }
    __syncthreads();

    {
        const int r = wid;
        float* prow = rows + (size_t)r * S_;
        float m = -INFINITY;
        for (int i = lane; i < nkc; i += 32) m = fmaxf(m, prow[i]);
        #pragma unroll
        for (int off = 16; off; off >>= 1) m = fmaxf(m, __shfl_xor_sync(0xffffffffu, m, off));
        float s = 0.f;
        for (int i = lane; i < nkc; i += 32) {
            float e = __expf(prow[i] - m);
            prow[i] = e;
            s += e;
        }
        #pragma unroll
        for (int off = 16; off; off >>= 1) s += __shfl_xor_sync(0xffffffffu, s, off);
        float inv = 1.f / s;
        for (int i = lane; i < nkc; i += 32) prow[i] *= inv;
    }
    __syncthreads();

    {
        size_t abase = (((size_t)b * H_ + h) * S_ + q0) * (size_t)S_;
        for (int i = tid; i < TQ * S_; i += 512) {
            int r   = i >> 11;
            int col = i & (S_ - 1);
            float v = 0.f;
            if (col <= q0 + r) v = rows[(size_t)r * S_ + col];
            attnw[abase + (size_t)r * S_ + col] = v;
        }
    }

    const int khalf = wid >> 3, ntile = wid & 7;
    const uint32_t pA_hi = smem_u32(Phi) + (uint32_t)(arow*(VST*2) + akoff + khalf*256);
    const uint32_t pA_lo = smem_u32(Plo) + (uint32_t)(arow*(VST*2) + akoff + khalf*256);
    const uint32_t vB_hi = smem_u32(VThi) + (uint32_t)((ntile*8 + rr)*(VST*2)
                          + (((lane >> 3) & 1) << 4) + khalf*256);
    const uint32_t vB_lo = vB_hi + (uint32_t)(64*VST*2);
    const size_t vgb = ((size_t)(b*H_ + h)) * 64 * S_;

    float oc[4] = {0.f, 0.f, 0.f, 0.f};
    for (int c = 0; c < nChunk; c++) {
        const int k0c = c * KCA;
        __syncthreads();
        #pragma unroll
        for (int it = 0; it < 8; it++) {
            int u = tid + it * 512;
            int which = u >> 11, uu = u & 2047;
            int d = uu >> 5, seg = uu & 31;
            const __nv_bfloat16* src = (which ? vtlo : vthi) + vgb
                + (size_t)d * S_ + k0c + seg*8;
            __nv_bfloat16* dst = (which ? VTlo : VThi) + d*VST + seg*8;
            *(uint4*)dst = *(const uint4*)src;
        }
        #pragma unroll
        for (int it = 0; it < 4; it++) {
            int p = tid + it * 512;
            int r = p >> 7, j2 = (p & 127) << 1;
            float v0 = rows[(size_t)r*S_ + k0c + j2];
            float v1 = rows[(size_t)r*S_ + k0c + j2 + 1];
            __nv_bfloat162 hb = __floats2bfloat162_rn(v0, v1);
            __nv_bfloat162 lb = __floats2bfloat162_rn(v0 - __bfloat162float(hb.x),
                                                      v1 - __bfloat162float(hb.y));
            *(uint32_t*)(Phi + r*VST + j2) = *(const uint32_t*)&hb;
            *(uint32_t*)(Plo + r*VST + j2) = *(const uint32_t*)&lb;
        }
        __syncthreads();

        #pragma unroll
        for (int ks = 0; ks < 8; ks++) {
            uint32_t ph[4], pl[4], vh[2], vl[2];
            ldm_x4(ph, pA_hi + ks*32);
            ldm_x4(pl, pA_lo + ks*32);
            ldm_x2(vh, vB_hi + ks*32);
            ldm_x2(vl, vB_lo + ks*32);
            mma_bf16(oc, ph, vh[0], vh[1]);
            mma_bf16(oc, ph, vl[0], vl[1]);
            mma_bf16(oc, pl, vh[0], vh[1]);
        }
    }

    __syncthreads();
    if (khalf == 1) {
        pbuf[gq*HD_ + ntile*8 + t2]       = oc[0];
        pbuf[gq*HD_ + ntile*8 + t2 + 1]   = oc[1];
        pbuf[(gq+8)*HD_ + ntile*8 + t2]   = oc[2];
        pbuf[(gq+8)*HD_ + ntile*8 + t2+1] = oc[3];
    }
    __syncthreads();
    if (khalf == 0) {
        const int col = h*HD_ + ntile*8 + t2;
        const size_t o0 = ((size_t)(b*S_ + q0 + gq)) * D_ + col;
        const size_t o1 = ((size_t)(b*S_ + q0 + gq + 8)) * D_ + col;
        float v00 = oc[0] + pbuf[gq*HD_ + ntile*8 + t2];
        float v01 = oc[1] + pbuf[gq*HD_ + ntile*8 + t2 + 1];
        float v10 = oc[2] + pbuf[(gq+8)*HD_ + ntile*8 + t2];
        float v11 = oc[3] + pbuf[(gq+8)*HD_ + ntile*8 + t2 + 1];
        __nv_bfloat162 h0 = __floats2bfloat162_rn(v00, v01);
        __nv_bfloat162 l0 = __floats2bfloat162_rn(v00 - __bfloat162float(h0.x),
                                                  v01 - __bfloat162float(h0.y));
        __nv_bfloat162 h1 = __floats2bfloat162_rn(v10, v11);
        __nv_bfloat162 l1 = __floats2bfloat162_rn(v10 - __bfloat162float(h1.x),
                                                  v11 - __bfloat162float(h1.y));
        *(uint32_t*)(aohi + o0) = *(const uint32_t*)&h0;
        *(uint32_t*)(aolo + o0) = *(const uint32_t*)&l0;
        *(uint32_t*)(aohi + o1) = *(const uint32_t*)&h1;
        *(uint32_t*)(aolo + o1) = *(const uint32_t*)&l1;
    }
}

// ---------------------------------------------------------------------------
extern "C" void kernel_launch(void* const* d_in, const int* in_sizes, int n_in,
                              void* d_out, int out_size)
{
    const float* x  = (const float*)d_in[0];
    const float* Wq = (const float*)d_in[1];
    const float* bq = (const float*)d_in[2];
    const float* Wk = (const float*)d_in[3];
    const float* bk = (const float*)d_in[4];
    const float* Wv = (const float*)d_in[5];
    const float* bv = (const float*)d_in[6];
    const float* Wo = (const float*)d_in[7];
    const float* bo = (const float*)d_in[8];

    float* out   = (float*)d_out;                       // [B,S,D]
    float* attnw = out + (size_t)B_ * S_ * D_;          // [B,H,S,S]

    float *q, *k, *v;
    __nv_bfloat16 *xhi, *xlo, *whi, *wlo, *aohi, *aolo;
    __nv_bfloat16 *qhi, *qlo, *khi, *klo, *vthi, *vtlo;
    cudaGetSymbolAddress((void**)&q,  g_q);
    cudaGetSymbolAddress((void**)&k,  g_k);
    cudaGetSymbolAddress((void**)&v,  g_v);
    cudaGetSymbolAddress((void**)&xhi, g_xhi);
    cudaGetSymbolAddress((void**)&xlo, g_xlo);
    cudaGetSymbolAddress((void**)&whi, g_whi);
    cudaGetSymbolAddress((void**)&wlo, g_wlo);
    cudaGetSymbolAddress((void**)&aohi, g_aohi);
    cudaGetSymbolAddress((void**)&aolo, g_aolo);
    cudaGetSymbolAddress((void**)&qhi, g_qhi);
    cudaGetSymbolAddress((void**)&qlo, g_qlo);
    cudaGetSymbolAddress((void**)&khi, g_khi);
    cudaGetSymbolAddress((void**)&klo, g_klo);
    cudaGetSymbolAddress((void**)&vthi, g_vthi);
    cudaGetSymbolAddress((void**)&vtlo, g_vtlo);

    const int M = MSZ;               // 4096
    const int WSZ = D_ * D_;         // 1048576
    const int NPX = M * D_ / 4;

    convert_split<<<(NPX + 255)/256, 256>>>((const float4*)x, (uint2*)xhi, (uint2*)xlo, NPX);
    const float* Ws[4] = { Wq, Wk, Wv, Wo };
    for (int i = 0; i < 4; i++)
        convert_split<<<(WSZ/4 + 255)/256, 256>>>((const float4*)Ws[i],
            (uint2*)(whi + (size_t)i*WSZ), (uint2*)(wlo + (size_t)i*WSZ), WSZ/4);

    cudaFuncSetAttribute(gemm_hmma, cudaFuncAttributeMaxDynamicSharedMemorySize, SM_GEMM);
    dim3 ggrid(D_ / 128, M / 128);   // (8, 32)

    // Q, K: write bf16 hi/lo directly. V: fp32 (transpose kernel consumes it).
    gemm_hmma<<<ggrid, 256, SM_GEMM>>>(xhi, xlo, whi + 0*(size_t)WSZ, wlo + 0*(size_t)WSZ,
                                       bq, nullptr, qhi, qlo, M, D_, D_);
    gemm_hmma<<<ggrid, 256, SM_GEMM>>>(xhi, xlo, whi + 1*(size_t)WSZ, wlo + 1*(size_t)WSZ,
                                       bk, nullptr, khi, klo, M, D_, D_);
    gemm_hmma<<<ggrid, 256, SM_GEMM>>>(xhi, xlo, whi + 2*(size_t)WSZ, wlo + 2*(size_t)WSZ,
                                       bv, v, nullptr, nullptr, M, D_, D_);

    {
        dim3 tg(S_/32, D_/32, B_);
        transpose_split_v<<<tg, 256>>>(v, vthi, vtlo);
    }

    cudaFuncSetAttribute(attn_hmma, cudaFuncAttributeMaxDynamicSharedMemorySize, SM_ATT);
    dim3 attn_grid(S_ / TQ, H_, B_);
    attn_hmma<<<attn_grid, 512, SM_ATT>>>(qhi, qlo, khi, klo, vthi, vtlo, attnw, aohi, aolo);

    gemm_hmma<<<ggrid, 256, SM_GEMM>>>(aohi, aolo, whi + 3*(size_t)WSZ, wlo + 3*(size_t)WSZ,
                                       bo, out, nullptr, nullptr, M, D_, D_);
}